// round 14
// baseline (speedup 1.0000x reference)
#include <cuda_runtime.h>
#include <cuda_bf16.h>
#include <cstdint>

#define N_NODES 50000
#define N_EDGES 800000
#define F_IN    512
#define F_HID   64
#define F_OUT   16

// ---------------- scratch (device globals; no allocations) ----------------
__device__ __align__(16) float g_dinv[N_NODES];
__device__ __align__(16) float g_H1[(size_t)N_NODES * F_HID];  // H1 * dinv[row]
__device__ __align__(16) float g_A1[(size_t)N_NODES * F_HID];
__device__ __align__(16) float g_H2[(size_t)N_NODES * F_OUT];  // H2 * dinv[row]
// W1^T in bf16 hi/lo: [64 n][512 k]
__device__ __align__(16) __nv_bfloat16 g_W1t_hi[(size_t)F_HID * F_IN];
__device__ __align__(16) __nv_bfloat16 g_W1t_lo[(size_t)F_HID * F_IN];

__device__ __forceinline__ uint32_t smem_u32(const void* p) {
    uint32_t a;
    asm("{ .reg .u64 t; cvta.to.shared.u64 t, %1; cvt.u32.u64 %0, t; }"
        : "=r"(a) : "l"(p));
    return a;
}

// ------- prep (launch 1): deg init (self loop) + W1 -> W1^T bf16 hi/lo -------
__global__ void k_prep(const float* __restrict__ W1, int n) {
    int t = blockIdx.x * blockDim.x + threadIdx.x;
    if (t < n) g_dinv[t] = 1.0f;
    if (t < F_HID * F_IN) {
        int n_ = t >> 9;          // /512
        int k  = t & 511;
        float w = W1[(size_t)k * F_HID + n_];
        __nv_bfloat16 h = __float2bfloat16_rn(w);
        __nv_bfloat16 l = __float2bfloat16_rn(w - __bfloat162float(h));
        g_W1t_hi[t] = h;
        g_W1t_lo[t] = l;
    }
}

// ------- (launch 2) degree count -------
__global__ void k_deg_count(const int* __restrict__ dst, int E, int n) {
    int e = blockIdx.x * blockDim.x + threadIdx.x;
    if (e >= E) return;
    int d = dst[e];
    if ((unsigned)d < (unsigned)n) atomicAdd(&g_dinv[d], 1.0f);
}

// ------- (launch 3) deg -> rsqrt -------
__global__ void k_rsqrt(int n) {
    int i = blockIdx.x * blockDim.x + threadIdx.x;
    if (i < n) g_dinv[i] = rsqrtf(g_dinv[i]);
}

// ====== GEMM1 (launch 4, profiled): mma.sync bf16x3, reg-prefetch pipelined ======
// H1' = (X@W1)*dinv[row] ; A1 init = H1'*dinv + b1
#define KC       64
#define NCHUNK   (F_IN / KC)        // 8
#define SROW     144                 // smem row stride bytes

__device__ __forceinline__ void ldmx4(uint32_t* r, uint32_t addr) {
    asm volatile("ldmatrix.sync.aligned.m8n8.x4.shared.b16 {%0,%1,%2,%3}, [%4];"
                 : "=r"(r[0]), "=r"(r[1]), "=r"(r[2]), "=r"(r[3]) : "r"(addr));
}
__device__ __forceinline__ void ldmx2(uint32_t* r, uint32_t addr) {
    asm volatile("ldmatrix.sync.aligned.m8n8.x2.shared.b16 {%0,%1}, [%2];"
                 : "=r"(r[0]), "=r"(r[1]) : "r"(addr));
}
__device__ __forceinline__ void mma16816(float* d, const uint32_t* a, const uint32_t* b) {
    asm volatile(
        "mma.sync.aligned.m16n8k16.row.col.f32.bf16.bf16.f32 "
        "{%0,%1,%2,%3}, {%4,%5,%6,%7}, {%8,%9}, {%0,%1,%2,%3};"
        : "+f"(d[0]), "+f"(d[1]), "+f"(d[2]), "+f"(d[3])
        : "r"(a[0]), "r"(a[1]), "r"(a[2]), "r"(a[3]), "r"(b[0]), "r"(b[1]));
}

__global__ void __launch_bounds__(128) k_gemm1_mma(const float* __restrict__ X,
                                                   const float* __restrict__ b1,
                                                   int N) {
    __shared__ __align__(16) uint8_t sm[4 * 64 * SROW];   // Ahi, Alo, Bhi, Blo
    uint8_t* p_ahi = sm;
    uint8_t* p_alo = sm + 64 * SROW;
    uint8_t* p_bhi = sm + 2 * 64 * SROW;
    uint8_t* p_blo = sm + 3 * 64 * SROW;
    const uint32_t s_ahi = smem_u32(p_ahi);
    const uint32_t s_alo = smem_u32(p_alo);
    const uint32_t s_bhi = smem_u32(p_bhi);
    const uint32_t s_blo = smem_u32(p_blo);

    const int tid  = threadIdx.x;
    const int wid  = tid >> 5;
    const int lane = tid & 31;
    const int block_row = blockIdx.x * 64;

    float acc[8][4];
#pragma unroll
    for (int g = 0; g < 8; g++)
#pragma unroll
        for (int j = 0; j < 4; j++) acc[g][j] = 0.f;

    const uint32_t a_row = 16 * wid + (lane & 15);
    const uint32_t a_c8  = (lane >> 4) * 8;
    const uint32_t b_row = lane & 7;
    const uint32_t b_c8  = ((lane >> 3) & 1) * 8;

    // per-thread staging indices
    const int ax_row = tid >> 1;              // A: 2 float4 per thread (rows tid/2)
    const int ax_c4a = (tid & 1) * 8;         //    covering c4 = 0..7 or 8..15
    const int bx_row = tid >> 1;              // B: rows tid/2
    const int bx_c   = (tid & 1) * 4;         //    uint4 cols 0..3 or 4..7

    // ---- stage chunk 0 ----
    float4 pa[8];
    uint4  pbh[4], pbl[4];
    {
        int gr = block_row + ax_row;
#pragma unroll
        for (int q = 0; q < 8; q++)
            pa[q] = (gr < N) ? *(const float4*)(X + (size_t)gr * F_IN + (ax_c4a + q) * 4)
                             : make_float4(0.f, 0.f, 0.f, 0.f);
#pragma unroll
        for (int q = 0; q < 4; q++) {
            size_t gsrc = (size_t)bx_row * F_IN + (bx_c + q) * 8;
            pbh[q] = *(const uint4*)(g_W1t_hi + gsrc);
            pbl[q] = *(const uint4*)(g_W1t_lo + gsrc);
        }
    }
    // convert + store chunk 0
#pragma unroll
    for (int q = 0; q < 8; q++) {
        float4 v = pa[q];
        __nv_bfloat162 h0 = __floats2bfloat162_rn(v.x, v.y);
        __nv_bfloat162 h1 = __floats2bfloat162_rn(v.z, v.w);
        __nv_bfloat162 l0 = __floats2bfloat162_rn(v.x - __low2float(h0),
                                                  v.y - __high2float(h0));
        __nv_bfloat162 l1 = __floats2bfloat162_rn(v.z - __low2float(h1),
                                                  v.w - __high2float(h1));
        uint32_t off = ax_row * SROW + (ax_c4a + q) * 8;
        *(uint32_t*)(p_ahi + off)     = *(uint32_t*)&h0;
        *(uint32_t*)(p_ahi + off + 4) = *(uint32_t*)&h1;
        *(uint32_t*)(p_alo + off)     = *(uint32_t*)&l0;
        *(uint32_t*)(p_alo + off + 4) = *(uint32_t*)&l1;
    }
#pragma unroll
    for (int q = 0; q < 4; q++) {
        uint32_t off = bx_row * SROW + (bx_c + q) * 16;
        *(uint4*)(p_bhi + off) = pbh[q];
        *(uint4*)(p_blo + off) = pbl[q];
    }
    __syncthreads();

    for (int chunk = 0; chunk < NCHUNK; chunk++) {
        // ---- prefetch chunk+1 into registers (overlaps with mma below) ----
        if (chunk + 1 < NCHUNK) {
            const int k0n = (chunk + 1) * KC;
            int gr = block_row + ax_row;
#pragma unroll
            for (int q = 0; q < 8; q++)
                pa[q] = (gr < N) ? *(const float4*)(X + (size_t)gr * F_IN + k0n + (ax_c4a + q) * 4)
                                 : make_float4(0.f, 0.f, 0.f, 0.f);
#pragma unroll
            for (int q = 0; q < 4; q++) {
                size_t gsrc = (size_t)bx_row * F_IN + k0n + (bx_c + q) * 8;
                pbh[q] = *(const uint4*)(g_W1t_hi + gsrc);
                pbl[q] = *(const uint4*)(g_W1t_lo + gsrc);
            }
        }

        // ---- compute on current smem ----
#pragma unroll
        for (int s = 0; s < 4; s++) {
            uint32_t ah[4], al[4];
            uint32_t aoff = a_row * SROW + (s * 16 + a_c8) * 2;
            ldmx4(ah, s_ahi + aoff);
            ldmx4(al, s_alo + aoff);
#pragma unroll
            for (int g = 0; g < 8; g++) {
                uint32_t bh[2], bl[2];
                uint32_t boff = (g * 8 + b_row) * SROW + (s * 16 + b_c8) * 2;
                ldmx2(bh, s_bhi + boff);
                ldmx2(bl, s_blo + boff);
                mma16816(acc[g], ah, bh);
                mma16816(acc[g], ah, bl);
                mma16816(acc[g], al, bh);
            }
        }

        // ---- convert + store prefetched chunk ----
        if (chunk + 1 < NCHUNK) {
            __syncthreads();   // all readers done with current smem
#pragma unroll
            for (int q = 0; q < 8; q++) {
                float4 v = pa[q];
                __nv_bfloat162 h0 = __floats2bfloat162_rn(v.x, v.y);
                __nv_bfloat162 h1 = __floats2bfloat162_rn(v.z, v.w);
                __nv_bfloat162 l0 = __floats2bfloat162_rn(v.x - __low2float(h0),
                                                          v.y - __high2float(h0));
                __nv_bfloat162 l1 = __floats2bfloat162_rn(v.z - __low2float(h1),
                                                          v.w - __high2float(h1));
                uint32_t off = ax_row * SROW + (ax_c4a + q) * 8;
                *(uint32_t*)(p_ahi + off)     = *(uint32_t*)&h0;
                *(uint32_t*)(p_ahi + off + 4) = *(uint32_t*)&h1;
                *(uint32_t*)(p_alo + off)     = *(uint32_t*)&l0;
                *(uint32_t*)(p_alo + off + 4) = *(uint32_t*)&l1;
            }
#pragma unroll
            for (int q = 0; q < 4; q++) {
                uint32_t off = bx_row * SROW + (bx_c + q) * 16;
                *(uint4*)(p_bhi + off) = pbh[q];
                *(uint4*)(p_blo + off) = pbl[q];
            }
            __syncthreads();   // new tile visible
        }
    }

    // epilogue: H1' = acc*dinv ; A1 init = H1'*dinv + b1
    int r0 = block_row + 16 * wid + (lane >> 2);
    int r1 = r0 + 8;
    int cb = (lane & 3) * 2;
    float s0 = (r0 < N) ? g_dinv[r0] : 0.f;
    float s1 = (r1 < N) ? g_dinv[r1] : 0.f;
#pragma unroll
    for (int g = 0; g < 8; g++) {
        int col = g * 8 + cb;
        float bx = b1[col], by = b1[col + 1];
        if (r0 < N) {
            float2 h = make_float2(acc[g][0] * s0, acc[g][1] * s0);
            *(float2*)(g_H1 + (size_t)r0 * F_HID + col) = h;
            *(float2*)(g_A1 + (size_t)r0 * F_HID + col) =
                make_float2(h.x * s0 + bx, h.y * s0 + by);
        }
        if (r1 < N) {
            float2 h = make_float2(acc[g][2] * s1, acc[g][3] * s1);
            *(float2*)(g_H1 + (size_t)r1 * F_HID + col) = h;
            *(float2*)(g_A1 + (size_t)r1 * F_HID + col) =
                make_float2(h.x * s1 + bx, h.y * s1 + by);
        }
    }
}

// ---------- layer-1 scatter: A1[dst] += H1'[src] * dinv[dst] (float4 atomic) ----
__global__ void k_scatter1(const int* __restrict__ src,
                           const int* __restrict__ dst, int E, int n) {
    long long t = (long long)blockIdx.x * blockDim.x + threadIdx.x;
    if (t >= (long long)E * (F_HID / 4)) return;
    int e  = (int)(t >> 4);
    int c4 = (int)(t & 15);
    int s = src[e];
    int d = dst[e];
    if ((unsigned)s >= (unsigned)n || (unsigned)d >= (unsigned)n) return;
    float nrm = g_dinv[d];
    float4 v = ((const float4*)g_H1)[(size_t)s * (F_HID / 4) + c4];
    v.x *= nrm; v.y *= nrm; v.z *= nrm; v.w *= nrm;
    atomicAdd(((float4*)g_A1) + (size_t)d * (F_HID / 4) + c4, v);
}

// ---------------- GEMM2: H2' = (relu(A1)@W2)*dinv ; out = H2'*dinv + b2 ------
__global__ void __launch_bounds__(256) k_gemm2(const float* __restrict__ W2,
                                               const float* __restrict__ b2,
                                               float* __restrict__ out, int N) {
    __shared__ float At[128][F_HID + 4];
    __shared__ float Ws[F_HID * F_OUT];

    const int tid = threadIdx.x;
    for (int i = tid; i < F_HID * F_OUT; i += 256) Ws[i] = W2[i];

    const int row0 = blockIdx.x * 128;
#pragma unroll
    for (int it = 0; it < 8; it++) {
        int idx = it * 256 + tid;
        int r   = idx >> 4;
        int c4  = idx & 15;
        int gr  = row0 + r;
        float4 v = (gr < N) ? ((const float4*)g_A1)[(size_t)gr * (F_HID / 4) + c4]
                            : make_float4(0.f, 0.f, 0.f, 0.f);
        v.x = fmaxf(v.x, 0.f); v.y = fmaxf(v.y, 0.f);
        v.z = fmaxf(v.z, 0.f); v.w = fmaxf(v.w, 0.f);
        *(float4*)&At[r][c4 * 4] = v;
    }
    __syncthreads();

    const int r  = tid >> 1;
    const int j0 = (tid & 1) * 8;
    const int gr = row0 + r;
    if (gr >= N) return;

    float acc[8];
#pragma unroll
    for (int j = 0; j < 8; j++) acc[j] = 0.f;
#pragma unroll
    for (int k = 0; k < F_HID; k++) {
        float xv = At[r][k];
#pragma unroll
        for (int j = 0; j < 8; j++) acc[j] += xv * Ws[k * F_OUT + j0 + j];
    }

    float s = g_dinv[gr];
    float4 bb0 = *(const float4*)(b2 + j0);
    float4 bb1 = *(const float4*)(b2 + j0 + 4);
    float4 h0 = make_float4(acc[0] * s, acc[1] * s, acc[2] * s, acc[3] * s);
    float4 h1 = make_float4(acc[4] * s, acc[5] * s, acc[6] * s, acc[7] * s);
    *(float4*)(g_H2 + (size_t)gr * F_OUT + j0)     = h0;
    *(float4*)(g_H2 + (size_t)gr * F_OUT + j0 + 4) = h1;
    float4 o0 = make_float4(h0.x * s + bb0.x, h0.y * s + bb0.y,
                            h0.z * s + bb0.z, h0.w * s + bb0.w);
    float4 o1 = make_float4(h1.x * s + bb1.x, h1.y * s + bb1.y,
                            h1.z * s + bb1.z, h1.w * s + bb1.w);
    *(float4*)(out + (size_t)gr * F_OUT + j0)     = o0;
    *(float4*)(out + (size_t)gr * F_OUT + j0 + 4) = o1;
}

// ---------- layer-2 scatter: out[dst] += H2'[src] * dinv[dst] (float4 atomic) ----
__global__ void k_scatter2(const int* __restrict__ src,
                           const int* __restrict__ dst,
                           float* __restrict__ out, int E, int n) {
    long long t = (long long)blockIdx.x * blockDim.x + threadIdx.x;
    if (t >= (long long)E * (F_OUT / 4)) return;
    int e  = (int)(t >> 2);
    int c4 = (int)(t & 3);
    int s = src[e];
    int d = dst[e];
    if ((unsigned)s >= (unsigned)n || (unsigned)d >= (unsigned)n) return;
    float nrm = g_dinv[d];
    float4 v = ((const float4*)g_H2)[(size_t)s * (F_OUT / 4) + c4];
    v.x *= nrm; v.y *= nrm; v.z *= nrm; v.w *= nrm;
    atomicAdd(((float4*)out) + (size_t)d * (F_OUT / 4) + c4, v);
}

// ---------------- launcher ----------------
extern "C" void kernel_launch(void* const* d_in, const int* in_sizes, int n_in,
                              void* d_out, int out_size) {
    const float* x  = (const float*)d_in[0];
    const int*   ei = (const int*)d_in[1];     // int32 edge_index
    const float* W1 = (const float*)d_in[2];
    const float* b1 = (const float*)d_in[3];
    const float* W2 = (const float*)d_in[4];
    const float* b2 = (const float*)d_in[5];
    float*       out = (float*)d_out;

    const int N = in_sizes[0] / F_IN;
    const int E = in_sizes[1] / 2;
    const int* src = ei;
    const int* dst = ei + E;

    const int T = 256;

    // launches 1-3: prep (grid covers BOTH ranges), count, rsqrt
    {
        int prep_work = (N > F_HID * F_IN) ? N : F_HID * F_IN;
        k_prep<<<(prep_work + T - 1) / T, T>>>(W1, N);
    }
    k_deg_count<<<(E + T - 1) / T, T>>>(dst, E, N);
    k_rsqrt<<<(N + T - 1) / T, T>>>(N);

    // launch 4 (profiled): pipelined tensor-core GEMM1 + fused epilogue
    k_gemm1_mma<<<(N + 63) / 64, 128>>>(x, b1, N);
    // launch 5: edge scatter layer 1
    {
        long long work = (long long)E * (F_HID / 4);
        k_scatter1<<<(unsigned)((work + T - 1) / T), T>>>(src, dst, E, N);
    }

    // launches 6-7: GEMM2 + edge scatter layer 2
    k_gemm2<<<(N + 127) / 128, T>>>(W2, b2, out, N);
    {
        long long work = (long long)E * (F_OUT / 4);
        k_scatter2<<<(unsigned)((work + T - 1) / T), T>>>(src, dst, out, E, N);
    }
}

// round 15
// speedup vs baseline: 1.0531x; 1.0531x over previous
#include <cuda_runtime.h>
#include <cuda_bf16.h>
#include <cstdint>

#define N_NODES 50000
#define N_EDGES 800000
#define F_IN    512
#define F_HID   64
#define F_OUT   16

// ---------------- scratch (device globals; no allocations) ----------------
__device__ __align__(16) float g_dinv[N_NODES];                // holds DEGREE (1+count)
__device__ __align__(16) float g_H1[(size_t)N_NODES * F_HID];  // H1 * dinv[row]
__device__ __align__(16) float g_A1[(size_t)N_NODES * F_HID];
__device__ __align__(16) float g_H2[(size_t)N_NODES * F_OUT];  // H2 * dinv[row]
// W1^T in bf16 hi/lo: [64 n][512 k]
__device__ __align__(16) __nv_bfloat16 g_W1t_hi[(size_t)F_HID * F_IN];
__device__ __align__(16) __nv_bfloat16 g_W1t_lo[(size_t)F_HID * F_IN];

__device__ __forceinline__ uint32_t smem_u32(const void* p) {
    uint32_t a;
    asm("{ .reg .u64 t; cvta.to.shared.u64 t, %1; cvt.u32.u64 %0, t; }"
        : "=r"(a) : "l"(p));
    return a;
}

// ------- prep (launch 1): deg init (self loop) + W1 -> W1^T bf16 hi/lo -------
// grid must cover max(N, F_HID*F_IN) threads!
__global__ void k_prep(const float* __restrict__ W1, int n) {
    int t = blockIdx.x * blockDim.x + threadIdx.x;
    if (t < n) g_dinv[t] = 1.0f;
    if (t < F_HID * F_IN) {
        int n_ = t >> 9;          // /512
        int k  = t & 511;
        float w = W1[(size_t)k * F_HID + n_];
        __nv_bfloat16 h = __float2bfloat16_rn(w);
        __nv_bfloat16 l = __float2bfloat16_rn(w - __bfloat162float(h));
        g_W1t_hi[t] = h;
        g_W1t_lo[t] = l;
    }
}

// ------- (launch 2) degree count -------
__global__ void k_deg_count(const int* __restrict__ dst, int E, int n) {
    int e = blockIdx.x * blockDim.x + threadIdx.x;
    if (e >= E) return;
    int d = dst[e];
    if ((unsigned)d < (unsigned)n) atomicAdd(&g_dinv[d], 1.0f);
}

// ====== GEMM1 (launch 3): mma.sync bf16x3 (R13 version, rsqrt inline) ======
// H1' = (X@W1)*rsqrt(deg[row]) ; A1 init = H1'*rsqrt(deg[row]) + b1
#define KC       64
#define NCHUNK   (F_IN / KC)        // 8
#define SROW     144                 // smem row stride bytes

__device__ __forceinline__ void ldmx4(uint32_t* r, uint32_t addr) {
    asm volatile("ldmatrix.sync.aligned.m8n8.x4.shared.b16 {%0,%1,%2,%3}, [%4];"
                 : "=r"(r[0]), "=r"(r[1]), "=r"(r[2]), "=r"(r[3]) : "r"(addr));
}
__device__ __forceinline__ void ldmx2(uint32_t* r, uint32_t addr) {
    asm volatile("ldmatrix.sync.aligned.m8n8.x2.shared.b16 {%0,%1}, [%2];"
                 : "=r"(r[0]), "=r"(r[1]) : "r"(addr));
}
__device__ __forceinline__ void mma16816(float* d, const uint32_t* a, const uint32_t* b) {
    asm volatile(
        "mma.sync.aligned.m16n8k16.row.col.f32.bf16.bf16.f32 "
        "{%0,%1,%2,%3}, {%4,%5,%6,%7}, {%8,%9}, {%0,%1,%2,%3};"
        : "+f"(d[0]), "+f"(d[1]), "+f"(d[2]), "+f"(d[3])
        : "r"(a[0]), "r"(a[1]), "r"(a[2]), "r"(a[3]), "r"(b[0]), "r"(b[1]));
}

__global__ void __launch_bounds__(128) k_gemm1_mma(const float* __restrict__ X,
                                                   const float* __restrict__ b1,
                                                   int N) {
    __shared__ __align__(16) uint8_t sm[4 * 64 * SROW];   // Ahi, Alo, Bhi, Blo
    uint8_t* p_ahi = sm;
    uint8_t* p_alo = sm + 64 * SROW;
    uint8_t* p_bhi = sm + 2 * 64 * SROW;
    uint8_t* p_blo = sm + 3 * 64 * SROW;
    const uint32_t s_ahi = smem_u32(p_ahi);
    const uint32_t s_alo = smem_u32(p_alo);
    const uint32_t s_bhi = smem_u32(p_bhi);
    const uint32_t s_blo = smem_u32(p_blo);

    const int tid  = threadIdx.x;
    const int wid  = tid >> 5;
    const int lane = tid & 31;
    const int block_row = blockIdx.x * 64;

    float acc[8][4];
#pragma unroll
    for (int g = 0; g < 8; g++)
#pragma unroll
        for (int j = 0; j < 4; j++) acc[g][j] = 0.f;

    const uint32_t a_row = 16 * wid + (lane & 15);
    const uint32_t a_c8  = (lane >> 4) * 8;
    const uint32_t b_row = lane & 7;
    const uint32_t b_c8  = ((lane >> 3) & 1) * 8;

    for (int chunk = 0; chunk < NCHUNK; chunk++) {
        const int k0 = chunk * KC;

#pragma unroll
        for (int it = 0; it < 8; it++) {
            int idx = it * 128 + tid;
            int row = idx >> 4;
            int c4  = idx & 15;
            int gr  = block_row + row;
            float4 v = (gr < N) ? *(const float4*)(X + (size_t)gr * F_IN + k0 + c4 * 4)
                                : make_float4(0.f, 0.f, 0.f, 0.f);
            __nv_bfloat162 h0 = __floats2bfloat162_rn(v.x, v.y);
            __nv_bfloat162 h1 = __floats2bfloat162_rn(v.z, v.w);
            __nv_bfloat162 l0 = __floats2bfloat162_rn(v.x - __low2float(h0),
                                                      v.y - __high2float(h0));
            __nv_bfloat162 l1 = __floats2bfloat162_rn(v.z - __low2float(h1),
                                                      v.w - __high2float(h1));
            uint32_t off = row * SROW + c4 * 8;
            *(uint32_t*)(p_ahi + off)     = *(uint32_t*)&h0;
            *(uint32_t*)(p_ahi + off + 4) = *(uint32_t*)&h1;
            *(uint32_t*)(p_alo + off)     = *(uint32_t*)&l0;
            *(uint32_t*)(p_alo + off + 4) = *(uint32_t*)&l1;
        }
#pragma unroll
        for (int it = 0; it < 4; it++) {
            int idx = it * 128 + tid;
            int row = idx >> 3;
            int c   = idx & 7;
            size_t gsrc = (size_t)row * F_IN + k0 + c * 8;
            uint32_t off = row * SROW + c * 16;
            *(uint4*)(p_bhi + off) = *(const uint4*)(g_W1t_hi + gsrc);
            *(uint4*)(p_blo + off) = *(const uint4*)(g_W1t_lo + gsrc);
        }
        __syncthreads();

#pragma unroll
        for (int s = 0; s < 4; s++) {
            uint32_t ah[4], al[4];
            uint32_t aoff = a_row * SROW + (s * 16 + a_c8) * 2;
            ldmx4(ah, s_ahi + aoff);
            ldmx4(al, s_alo + aoff);
#pragma unroll
            for (int g = 0; g < 8; g++) {
                uint32_t bh[2], bl[2];
                uint32_t boff = (g * 8 + b_row) * SROW + (s * 16 + b_c8) * 2;
                ldmx2(bh, s_bhi + boff);
                ldmx2(bl, s_blo + boff);
                mma16816(acc[g], ah, bh);
                mma16816(acc[g], ah, bl);
                mma16816(acc[g], al, bh);
            }
        }
        __syncthreads();
    }

    // epilogue: s = rsqrt(deg) ; H1' = acc*s ; A1 init = H1'*s + b1
    int r0 = block_row + 16 * wid + (lane >> 2);
    int r1 = r0 + 8;
    int cb = (lane & 3) * 2;
    float s0 = (r0 < N) ? rsqrtf(g_dinv[r0]) : 0.f;
    float s1 = (r1 < N) ? rsqrtf(g_dinv[r1]) : 0.f;
#pragma unroll
    for (int g = 0; g < 8; g++) {
        int col = g * 8 + cb;
        float bx = b1[col], by = b1[col + 1];
        if (r0 < N) {
            float2 h = make_float2(acc[g][0] * s0, acc[g][1] * s0);
            *(float2*)(g_H1 + (size_t)r0 * F_HID + col) = h;
            *(float2*)(g_A1 + (size_t)r0 * F_HID + col) =
                make_float2(h.x * s0 + bx, h.y * s0 + by);
        }
        if (r1 < N) {
            float2 h = make_float2(acc[g][2] * s1, acc[g][3] * s1);
            *(float2*)(g_H1 + (size_t)r1 * F_HID + col) = h;
            *(float2*)(g_A1 + (size_t)r1 * F_HID + col) =
                make_float2(h.x * s1 + bx, h.y * s1 + by);
        }
    }
}

// ---- layer-1 scatter (launch 4, PROFILED): A1[dst] += H1'[src]*rsqrt(deg[dst]) ----
__global__ void k_scatter1(const int* __restrict__ src,
                           const int* __restrict__ dst, int E, int n) {
    long long t = (long long)blockIdx.x * blockDim.x + threadIdx.x;
    if (t >= (long long)E * (F_HID / 4)) return;
    int e  = (int)(t >> 4);
    int c4 = (int)(t & 15);
    int s = src[e];
    int d = dst[e];
    if ((unsigned)s >= (unsigned)n || (unsigned)d >= (unsigned)n) return;
    float nrm = rsqrtf(g_dinv[d]);
    float4 v = ((const float4*)g_H1)[(size_t)s * (F_HID / 4) + c4];
    v.x *= nrm; v.y *= nrm; v.z *= nrm; v.w *= nrm;
    atomicAdd(((float4*)g_A1) + (size_t)d * (F_HID / 4) + c4, v);
}

// ---------------- GEMM2: H2' = (relu(A1)@W2)*s ; out = H2'*s + b2 ------
__global__ void __launch_bounds__(256) k_gemm2(const float* __restrict__ W2,
                                               const float* __restrict__ b2,
                                               float* __restrict__ out, int N) {
    __shared__ float At[128][F_HID + 4];
    __shared__ float Ws[F_HID * F_OUT];

    const int tid = threadIdx.x;
    for (int i = tid; i < F_HID * F_OUT; i += 256) Ws[i] = W2[i];

    const int row0 = blockIdx.x * 128;
#pragma unroll
    for (int it = 0; it < 8; it++) {
        int idx = it * 256 + tid;
        int r   = idx >> 4;
        int c4  = idx & 15;
        int gr  = row0 + r;
        float4 v = (gr < N) ? ((const float4*)g_A1)[(size_t)gr * (F_HID / 4) + c4]
                            : make_float4(0.f, 0.f, 0.f, 0.f);
        v.x = fmaxf(v.x, 0.f); v.y = fmaxf(v.y, 0.f);
        v.z = fmaxf(v.z, 0.f); v.w = fmaxf(v.w, 0.f);
        *(float4*)&At[r][c4 * 4] = v;
    }
    __syncthreads();

    const int r  = tid >> 1;
    const int j0 = (tid & 1) * 8;
    const int gr = row0 + r;
    if (gr >= N) return;

    float acc[8];
#pragma unroll
    for (int j = 0; j < 8; j++) acc[j] = 0.f;
#pragma unroll
    for (int k = 0; k < F_HID; k++) {
        float xv = At[r][k];
#pragma unroll
        for (int j = 0; j < 8; j++) acc[j] += xv * Ws[k * F_OUT + j0 + j];
    }

    float s = rsqrtf(g_dinv[gr]);
    float4 bb0 = *(const float4*)(b2 + j0);
    float4 bb1 = *(const float4*)(b2 + j0 + 4);
    float4 h0 = make_float4(acc[0] * s, acc[1] * s, acc[2] * s, acc[3] * s);
    float4 h1 = make_float4(acc[4] * s, acc[5] * s, acc[6] * s, acc[7] * s);
    *(float4*)(g_H2 + (size_t)gr * F_OUT + j0)     = h0;
    *(float4*)(g_H2 + (size_t)gr * F_OUT + j0 + 4) = h1;
    float4 o0 = make_float4(h0.x * s + bb0.x, h0.y * s + bb0.y,
                            h0.z * s + bb0.z, h0.w * s + bb0.w);
    float4 o1 = make_float4(h1.x * s + bb1.x, h1.y * s + bb1.y,
                            h1.z * s + bb1.z, h1.w * s + bb1.w);
    *(float4*)(out + (size_t)gr * F_OUT + j0)     = o0;
    *(float4*)(out + (size_t)gr * F_OUT + j0 + 4) = o1;
}

// ---------- layer-2 scatter: out[dst] += H2'[src] * rsqrt(deg[dst]) ----------
__global__ void k_scatter2(const int* __restrict__ src,
                           const int* __restrict__ dst,
                           float* __restrict__ out, int E, int n) {
    long long t = (long long)blockIdx.x * blockDim.x + threadIdx.x;
    if (t >= (long long)E * (F_OUT / 4)) return;
    int e  = (int)(t >> 2);
    int c4 = (int)(t & 3);
    int s = src[e];
    int d = dst[e];
    if ((unsigned)s >= (unsigned)n || (unsigned)d >= (unsigned)n) return;
    float nrm = rsqrtf(g_dinv[d]);
    float4 v = ((const float4*)g_H2)[(size_t)s * (F_OUT / 4) + c4];
    v.x *= nrm; v.y *= nrm; v.z *= nrm; v.w *= nrm;
    atomicAdd(((float4*)out) + (size_t)d * (F_OUT / 4) + c4, v);
}

// ---------------- launcher ----------------
extern "C" void kernel_launch(void* const* d_in, const int* in_sizes, int n_in,
                              void* d_out, int out_size) {
    const float* x  = (const float*)d_in[0];
    const int*   ei = (const int*)d_in[1];     // int32 edge_index
    const float* W1 = (const float*)d_in[2];
    const float* b1 = (const float*)d_in[3];
    const float* W2 = (const float*)d_in[4];
    const float* b2 = (const float*)d_in[5];
    float*       out = (float*)d_out;

    const int N = in_sizes[0] / F_IN;
    const int E = in_sizes[1] / 2;
    const int* src = ei;
    const int* dst = ei + E;

    const int T = 256;

    // launch 1: prep (grid covers BOTH ranges)
    {
        int prep_work = (N > F_HID * F_IN) ? N : F_HID * F_IN;
        k_prep<<<(prep_work + T - 1) / T, T>>>(W1, N);
    }
    // launch 2: degree count
    k_deg_count<<<(E + T - 1) / T, T>>>(dst, E, N);

    // launch 3: tensor-core GEMM1 + fused epilogue (rsqrt inline)
    k_gemm1_mma<<<(N + 63) / 64, 128>>>(x, b1, N);

    // launch 4 (PROFILED): edge scatter layer 1
    {
        long long work = (long long)E * (F_HID / 4);
        k_scatter1<<<(unsigned)((work + T - 1) / T), T>>>(src, dst, E, N);
    }

    // launches 5-6: GEMM2 + edge scatter layer 2
    k_gemm2<<<(N + 127) / 128, T>>>(W2, b2, out, N);
    {
        long long work = (long long)E * (F_OUT / 4);
        k_scatter2<<<(unsigned)((work + T - 1) / T), T>>>(src, dst, out, E, N);
    }
}